// round 2
// baseline (speedup 1.0000x reference)
#include <cuda_runtime.h>
#include <cuda_bf16.h>

#define L_SEQ 2304
#define DM 128
#define DI 256
#define DS 16
#define DR 8
#define NCH 36     // scan chunks
#define CT 64      // steps per chunk (NCH*CT == L_SEQ)
#define DEPTH 8

// ---------------- scratch (device globals; no allocation allowed) ----------
__device__ float g_seq[L_SEQ * DM];
__device__ float g_xi [L_SEQ * DI];
__device__ float g_zs [L_SEQ * DI];   // silu(z), precomputed in GEMM1 epilogue
__device__ float g_xc [L_SEQ * DI];
__device__ float g_dt [L_SEQ * DI];
__device__ float g_Bs [L_SEQ * DS];
__device__ float g_Cs [L_SEQ * DS];
__device__ float g_y  [L_SEQ * DI];
__device__ float g_P  [NCH * DI * DS];
__device__ float g_hN [NCH * DI * DS];
__device__ float g_hin[NCH * DI * DS];

__device__ __forceinline__ float siluf(float v) {
    return v / (1.0f + __expf(-v));
}
__device__ __forceinline__ float softplusf(float v) {
    return v > 20.0f ? v : log1pf(__expf(v));
}

// ---------------- transpose in: x[128][2304] -> g_seq[2304][128] -----------
__global__ void k_in_transpose(const float* __restrict__ x)
{
    __shared__ float tile[32][33];
    int tx = threadIdx.x, ty = threadIdx.y;
    int bx = blockIdx.x, by = blockIdx.y;   // bx over L tiles, by over C tiles
    #pragma unroll
    for (int i = 0; i < 32; i += 8)
        tile[ty + i][tx] = x[(by * 32 + ty + i) * L_SEQ + bx * 32 + tx];
    __syncthreads();
    #pragma unroll
    for (int i = 0; i < 32; i += 8)
        g_seq[(bx * 32 + ty + i) * DM + by * 32 + tx] = tile[tx][ty + i];
}

// ---------------- transpose out: g_seq[2304][128] -> out[128][2304] --------
__global__ void k_out_transpose(float* __restrict__ out)
{
    __shared__ float tile[32][33];
    int tx = threadIdx.x, ty = threadIdx.y;
    int bx = blockIdx.x, by = blockIdx.y;   // bx over C tiles, by over L tiles
    #pragma unroll
    for (int i = 0; i < 32; i += 8)
        tile[ty + i][tx] = g_seq[(by * 32 + ty + i) * DM + bx * 32 + tx];
    __syncthreads();
    #pragma unroll
    for (int i = 0; i < 32; i += 8)
        out[(bx * 32 + ty + i) * L_SEQ + by * 32 + tx] = tile[tx][ty + i];
}

// ---------------- GEMM1: xz = seq @ W_in, split -> xi, silu(z) --------------
// M=2304 (16 rows/block), N=512, K=128. 256 threads, each 2 adjacent cols.
__global__ void k_gemm_in(const float* __restrict__ W)
{
    __shared__ float a_s[16 * 128];   // [r][k]
    int tid = threadIdx.x;
    int r0 = blockIdx.x * 16;
    for (int idx = tid; idx < 16 * 128; idx += 256)
        a_s[idx] = g_seq[r0 * DM + idx];
    __syncthreads();

    float acc0[16], acc1[16];
    #pragma unroll
    for (int r = 0; r < 16; r++) { acc0[r] = 0.f; acc1[r] = 0.f; }
    int j = tid * 2;
    const float* Wp = W + j;
    #pragma unroll 4
    for (int k = 0; k < 128; k++) {
        float2 b = *reinterpret_cast<const float2*>(Wp + k * 512);
        #pragma unroll
        for (int r = 0; r < 16; r++) {
            float a = a_s[r * 128 + k];
            acc0[r] = fmaf(a, b.x, acc0[r]);
            acc1[r] = fmaf(a, b.y, acc1[r]);
        }
    }
    if (j < 256) {
        #pragma unroll
        for (int r = 0; r < 16; r++) {
            g_xi[(r0 + r) * DI + j]     = acc0[r];
            g_xi[(r0 + r) * DI + j + 1] = acc1[r];
        }
    } else {
        int q = j - 256;
        #pragma unroll
        for (int r = 0; r < 16; r++) {
            g_zs[(r0 + r) * DI + q]     = siluf(acc0[r]);
            g_zs[(r0 + r) * DI + q + 1] = siluf(acc1[r]);
        }
    }
}

// ------------- conv(+silu) + x-proj + dt(softplus) + Bs/Cs split -----------
// one block = 16 sequence rows, 256 threads
__global__ void k_conv_proj(const float* __restrict__ cw,
                            const float* __restrict__ cb,
                            const float* __restrict__ Wx,
                            const float* __restrict__ Wdt,
                            const float* __restrict__ bdt)
{
    __shared__ float xc_s[16 * 256];
    __shared__ float dbl_s[16 * 40];
    int tid = threadIdx.x;
    int r0 = blockIdx.x * 16;
    int d = tid;

    // phase 1: causal depthwise conv (k=4) + silu
    float4 c4 = *reinterpret_cast<const float4*>(cw + d * 4);
    float cbd = cb[d];
    #pragma unroll
    for (int r = 0; r < 16; r++) {
        int l = r0 + r;
        float x0 = (l >= 3) ? g_xi[(l - 3) * DI + d] : 0.f;
        float x1 = (l >= 2) ? g_xi[(l - 2) * DI + d] : 0.f;
        float x2 = (l >= 1) ? g_xi[(l - 1) * DI + d] : 0.f;
        float x3 = g_xi[l * DI + d];
        float acc = cbd;
        acc = fmaf(x0, c4.x, acc);
        acc = fmaf(x1, c4.y, acc);
        acc = fmaf(x2, c4.z, acc);
        acc = fmaf(x3, c4.w, acc);
        float v = siluf(acc);
        xc_s[r * 256 + d] = v;
        g_xc[l * DI + d]  = v;
    }
    __syncthreads();

    // phase 2: dbl = xc @ Wx  (16 rows x 40 cols, K=256)
    for (int o = tid; o < 16 * 40; o += 256) {
        int r = o / 40, cc = o - r * 40;
        const float* xr = &xc_s[r * 256];
        float sum = 0.f;
        #pragma unroll 8
        for (int k = 0; k < 256; k++)
            sum = fmaf(xr[k], Wx[k * 40 + cc], sum);
        dbl_s[r * 40 + cc] = sum;
    }
    __syncthreads();

    // phase 3: dt = softplus(dt_r @ Wdt + b_dt)
    {
        float bv = bdt[d];
        #pragma unroll 2
        for (int r = 0; r < 16; r++) {
            float v = bv;
            #pragma unroll
            for (int jj = 0; jj < 8; jj++)
                v = fmaf(dbl_s[r * 40 + jj], Wdt[jj * 256 + d], v);
            g_dt[(r0 + r) * DI + d] = softplusf(v);
        }
    }
    // phase 4: Bs / Cs split
    for (int idx = tid; idx < 16 * 32; idx += 256) {
        int r = idx >> 5, q = idx & 31;
        float val = dbl_s[r * 40 + 8 + q];
        if (q < 16) g_Bs[(r0 + r) * DS + q]       = val;
        else        g_Cs[(r0 + r) * DS + (q - 16)] = val;
    }
}

// ---------------- scan phase 1: per-chunk (prod dA, local h) ----------------
// grid (16 channel-groups, NCH chunks), 256 threads = 16 ch x 16 states
__global__ void k_scan1(const float* __restrict__ Alog)
{
    __shared__ float dt_s[CT * 16], xc_s[CT * 16], Bs_s[CT * 16];
    int tid = threadIdx.x;
    int chBase = blockIdx.x * 16;
    int c = blockIdx.y;
    int l0 = c * CT;
    for (int idx = tid; idx < CT * 16; idx += 256) {
        int t = idx >> 4, e = idx & 15;
        dt_s[idx] = g_dt[(l0 + t) * DI + chBase + e];
        xc_s[idx] = g_xc[(l0 + t) * DI + chBase + e];
        Bs_s[idx] = g_Bs[(l0 + t) * DS + e];
    }
    __syncthreads();

    int w = tid >> 5, lane = tid & 31;
    int ch = 2 * w + (lane >> 4);
    int s = lane & 15;
    int dG = chBase + ch;
    float negA = -__expf(Alog[dG * DS + s]);

    float h = 0.f, P = 1.f;
    #pragma unroll 4
    for (int t = 0; t < CT; t++) {
        float dtv = dt_s[t * 16 + ch];
        float b   = Bs_s[t * 16 + s];
        float dA  = __expf(dtv * negA);
        P *= dA;
        h = fmaf(dA, h, dtv * xc_s[t * 16 + ch] * b);
    }
    int o = (c * DI + dG) * DS + s;
    g_P[o]  = P;
    g_hN[o] = h;
}

// ---------------- scan phase 2: sequential combine over chunks -------------
__global__ void k_scan2()
{
    int ds = blockIdx.x * 256 + threadIdx.x;   // 0..4095
    float carry = 0.f;
    #pragma unroll 4
    for (int c = 0; c < NCH; c++) {
        g_hin[c * (DI * DS) + ds] = carry;
        carry = fmaf(g_P[c * (DI * DS) + ds], carry, g_hN[c * (DI * DS) + ds]);
    }
}

// ---------------- scan phase 3: replay with carry, produce gated y ---------
__global__ void k_scan3(const float* __restrict__ Alog,
                        const float* __restrict__ Dp)
{
    __shared__ float dt_s[CT * 16], xc_s[CT * 16], zs_s[CT * 16];
    __shared__ float Bs_s[CT * 16], Cs_s[CT * 16];
    int tid = threadIdx.x;
    int chBase = blockIdx.x * 16;
    int c = blockIdx.y;
    int l0 = c * CT;
    for (int idx = tid; idx < CT * 16; idx += 256) {
        int t = idx >> 4, e = idx & 15;
        dt_s[idx] = g_dt[(l0 + t) * DI + chBase + e];
        xc_s[idx] = g_xc[(l0 + t) * DI + chBase + e];
        zs_s[idx] = g_zs[(l0 + t) * DI + chBase + e];
        Bs_s[idx] = g_Bs[(l0 + t) * DS + e];
        Cs_s[idx] = g_Cs[(l0 + t) * DS + e];
    }
    __syncthreads();

    int w = tid >> 5, lane = tid & 31;
    int ch = 2 * w + (lane >> 4);
    int s = lane & 15;
    int dG = chBase + ch;
    float negA  = -__expf(Alog[dG * DS + s]);
    float dskip = Dp[dG];

    float h = g_hin[(c * DI + dG) * DS + s];
    #pragma unroll 4
    for (int t = 0; t < CT; t++) {
        float dtv = dt_s[t * 16 + ch];
        float xcv = xc_s[t * 16 + ch];
        float b   = Bs_s[t * 16 + s];
        float dA  = __expf(dtv * negA);
        h = fmaf(dA, h, dtv * xcv * b);
        float p = h * Cs_s[t * 16 + s];
        p += __shfl_xor_sync(0xffffffffu, p, 8);
        p += __shfl_xor_sync(0xffffffffu, p, 4);
        p += __shfl_xor_sync(0xffffffffu, p, 2);
        p += __shfl_xor_sync(0xffffffffu, p, 1);
        if (s == 0)
            g_y[(l0 + t) * DI + dG] = (p + dskip * xcv) * zs_s[t * 16 + ch];
    }
}

// ---------------- out GEMM + fused RMSNorm ----------------------------------
// M=2304 (16 rows/block), N=128, K=256; 128 threads, one col each
__global__ void k_gemm_out(const float* __restrict__ Wo,
                           const float* __restrict__ rmsw)
{
    __shared__ float y_s[16 * 256];
    __shared__ float red[16 * 4];
    int tid = threadIdx.x;
    int r0 = blockIdx.x * 16;
    for (int idx = tid; idx < 16 * 256; idx += 128)
        y_s[idx] = g_y[r0 * DI + idx];
    __syncthreads();

    float acc[16];
    #pragma unroll
    for (int r = 0; r < 16; r++) acc[r] = 0.f;
    #pragma unroll 2
    for (int k = 0; k < 256; k++) {
        float wv = Wo[k * DM + tid];
        #pragma unroll
        for (int r = 0; r < 16; r++)
            acc[r] = fmaf(y_s[r * 256 + k], wv, acc[r]);
    }

    int lane = tid & 31, w = tid >> 5;
    #pragma unroll
    for (int r = 0; r < 16; r++) {
        float v = acc[r] * acc[r];
        v += __shfl_xor_sync(0xffffffffu, v, 16);
        v += __shfl_xor_sync(0xffffffffu, v, 8);
        v += __shfl_xor_sync(0xffffffffu, v, 4);
        v += __shfl_xor_sync(0xffffffffu, v, 2);
        v += __shfl_xor_sync(0xffffffffu, v, 1);
        if (lane == 0) red[r * 4 + w] = v;
    }
    __syncthreads();

    float rw = rmsw[tid];
    #pragma unroll
    for (int r = 0; r < 16; r++) {
        float ss = red[r * 4 + 0] + red[r * 4 + 1] + red[r * 4 + 2] + red[r * 4 + 3];
        float sc = rsqrtf(ss * (1.0f / 128.0f) + 1e-5f);
        g_seq[(r0 + r) * DM + tid] = acc[r] * sc * rw;
    }
}

// ---------------------------------------------------------------------------
extern "C" void kernel_launch(void* const* d_in, const int* in_sizes, int n_in,
                              void* d_out, int out_size)
{
    const float* x      = (const float*)d_in[0];
    const float* W_in   = (const float*)d_in[1];
    const float* conv_w = (const float*)d_in[2];
    const float* conv_b = (const float*)d_in[3];
    const float* W_xprj = (const float*)d_in[4];
    const float* W_dt   = (const float*)d_in[5];
    const float* b_dt   = (const float*)d_in[6];
    const float* A_log  = (const float*)d_in[7];
    const float* D_skip = (const float*)d_in[8];
    const float* W_out  = (const float*)d_in[9];
    const float* rms_w  = (const float*)d_in[10];
    float* out = (float*)d_out;

    dim3 tb(32, 8);
    k_in_transpose<<<dim3(L_SEQ / 32, DM / 32), tb>>>(x);

    for (int layer = 0; layer < DEPTH; ++layer) {
        const float* Wi  = W_in   + layer * DM * 2 * DI;
        const float* cw  = conv_w + layer * DI * 4;
        const float* cb  = conv_b + layer * DI;
        const float* Wx  = W_xprj + layer * DI * (DR + 2 * DS);
        const float* Wdt = W_dt   + layer * DR * DI;
        const float* bdt = b_dt   + layer * DI;
        const float* Al  = A_log  + layer * DI * DS;
        const float* Dp  = D_skip + layer * DI;
        const float* Wo  = W_out  + layer * DI * DM;
        const float* rw  = rms_w  + layer * DM;

        k_gemm_in  <<<L_SEQ / 16, 256>>>(Wi);
        k_conv_proj<<<L_SEQ / 16, 256>>>(cw, cb, Wx, Wdt, bdt);
        k_scan1    <<<dim3(DI / 16, NCH), 256>>>(Al);
        k_scan2    <<<(DI * DS) / 256, 256>>>();
        k_scan3    <<<dim3(DI / 16, NCH), 256>>>(Al, Dp);
        k_gemm_out <<<L_SEQ / 16, 128>>>(Wo, rw);
    }

    k_out_transpose<<<dim3(DM / 32, L_SEQ / 32), tb>>>(out);
}

// round 3
// speedup vs baseline: 1.0005x; 1.0005x over previous
#include <cuda_runtime.h>
#include <cuda_bf16.h>

#define L_SEQ 2304
#define DM 128
#define DI 256
#define DS 16
#define DR 8
#define NCH 36     // scan chunks
#define CT 64      // steps per chunk (NCH*CT == L_SEQ)
#define DEPTH 8

// ---------------- scratch (device globals; no allocation allowed) ----------
__device__ float g_seq[L_SEQ * DM];
__device__ float g_xi [L_SEQ * DI];
__device__ float g_zs [L_SEQ * DI];   // silu(z), precomputed in GEMM1 epilogue
__device__ float g_xc [L_SEQ * DI];
__device__ float g_dt [L_SEQ * DI];
__device__ float g_Bs [L_SEQ * DS];
__device__ float g_Cs [L_SEQ * DS];
__device__ float g_y  [L_SEQ * DI];
__device__ float g_P  [NCH * DI * DS];
__device__ float g_hN [NCH * DI * DS];
__device__ float g_hin[NCH * DI * DS];

__device__ __forceinline__ float siluf(float v) {
    return v / (1.0f + __expf(-v));
}
__device__ __forceinline__ float softplusf(float v) {
    return v > 20.0f ? v : log1pf(__expf(v));
}

// ---------------- transpose in: x[128][2304] -> g_seq[2304][128] -----------
__global__ void k_in_transpose(const float* __restrict__ x)
{
    __shared__ float tile[32][33];
    int tx = threadIdx.x, ty = threadIdx.y;
    int bx = blockIdx.x, by = blockIdx.y;   // bx over L tiles, by over C tiles
    #pragma unroll
    for (int i = 0; i < 32; i += 8)
        tile[ty + i][tx] = x[(by * 32 + ty + i) * L_SEQ + bx * 32 + tx];
    __syncthreads();
    #pragma unroll
    for (int i = 0; i < 32; i += 8)
        g_seq[(bx * 32 + ty + i) * DM + by * 32 + tx] = tile[tx][ty + i];
}

// ---------------- transpose out: g_seq[2304][128] -> out[128][2304] --------
__global__ void k_out_transpose(float* __restrict__ out)
{
    __shared__ float tile[32][33];
    int tx = threadIdx.x, ty = threadIdx.y;
    int bx = blockIdx.x, by = blockIdx.y;   // bx over C tiles, by over L tiles
    #pragma unroll
    for (int i = 0; i < 32; i += 8)
        tile[ty + i][tx] = g_seq[(by * 32 + ty + i) * DM + bx * 32 + tx];
    __syncthreads();
    #pragma unroll
    for (int i = 0; i < 32; i += 8)
        out[(bx * 32 + ty + i) * L_SEQ + by * 32 + tx] = tile[tx][ty + i];
}

// ---------------- GEMM1: xz = seq @ W_in, split -> xi, silu(z) --------------
// M=2304 (16 rows/block), N=512, K=128. 256 threads, each 2 adjacent cols.
__global__ void k_gemm_in(const float* __restrict__ W)
{
    __shared__ float a_s[16 * 128];   // [r][k]
    int tid = threadIdx.x;
    int r0 = blockIdx.x * 16;
    for (int idx = tid; idx < 16 * 128; idx += 256)
        a_s[idx] = g_seq[r0 * DM + idx];
    __syncthreads();

    float acc0[16], acc1[16];
    #pragma unroll
    for (int r = 0; r < 16; r++) { acc0[r] = 0.f; acc1[r] = 0.f; }
    int j = tid * 2;
    const float* Wp = W + j;
    #pragma unroll 4
    for (int k = 0; k < 128; k++) {
        float2 b = *reinterpret_cast<const float2*>(Wp + k * 512);
        #pragma unroll
        for (int r = 0; r < 16; r++) {
            float a = a_s[r * 128 + k];
            acc0[r] = fmaf(a, b.x, acc0[r]);
            acc1[r] = fmaf(a, b.y, acc1[r]);
        }
    }
    if (j < 256) {
        #pragma unroll
        for (int r = 0; r < 16; r++) {
            g_xi[(r0 + r) * DI + j]     = acc0[r];
            g_xi[(r0 + r) * DI + j + 1] = acc1[r];
        }
    } else {
        int q = j - 256;
        #pragma unroll
        for (int r = 0; r < 16; r++) {
            g_zs[(r0 + r) * DI + q]     = siluf(acc0[r]);
            g_zs[(r0 + r) * DI + q + 1] = siluf(acc1[r]);
        }
    }
}

// ------------- conv(+silu) + x-proj + dt(softplus) + Bs/Cs split -----------
// one block = 16 sequence rows, 256 threads
__global__ void k_conv_proj(const float* __restrict__ cw,
                            const float* __restrict__ cb,
                            const float* __restrict__ Wx,
                            const float* __restrict__ Wdt,
                            const float* __restrict__ bdt)
{
    __shared__ float xc_s[16 * 256];
    __shared__ float dbl_s[16 * 40];
    int tid = threadIdx.x;
    int r0 = blockIdx.x * 16;
    int d = tid;

    // phase 1: causal depthwise conv (k=4) + silu
    float4 c4 = *reinterpret_cast<const float4*>(cw + d * 4);
    float cbd = cb[d];
    #pragma unroll
    for (int r = 0; r < 16; r++) {
        int l = r0 + r;
        float x0 = (l >= 3) ? g_xi[(l - 3) * DI + d] : 0.f;
        float x1 = (l >= 2) ? g_xi[(l - 2) * DI + d] : 0.f;
        float x2 = (l >= 1) ? g_xi[(l - 1) * DI + d] : 0.f;
        float x3 = g_xi[l * DI + d];
        float acc = cbd;
        acc = fmaf(x0, c4.x, acc);
        acc = fmaf(x1, c4.y, acc);
        acc = fmaf(x2, c4.z, acc);
        acc = fmaf(x3, c4.w, acc);
        float v = siluf(acc);
        xc_s[r * 256 + d] = v;
        g_xc[l * DI + d]  = v;
    }
    __syncthreads();

    // phase 2: dbl = xc @ Wx  (16 rows x 40 cols, K=256)
    for (int o = tid; o < 16 * 40; o += 256) {
        int r = o / 40, cc = o - r * 40;
        const float* xr = &xc_s[r * 256];
        float sum = 0.f;
        #pragma unroll 8
        for (int k = 0; k < 256; k++)
            sum = fmaf(xr[k], Wx[k * 40 + cc], sum);
        dbl_s[r * 40 + cc] = sum;
    }
    __syncthreads();

    // phase 3: dt = softplus(dt_r @ Wdt + b_dt)
    {
        float bv = bdt[d];
        #pragma unroll 2
        for (int r = 0; r < 16; r++) {
            float v = bv;
            #pragma unroll
            for (int jj = 0; jj < 8; jj++)
                v = fmaf(dbl_s[r * 40 + jj], Wdt[jj * 256 + d], v);
            g_dt[(r0 + r) * DI + d] = softplusf(v);
        }
    }
    // phase 4: Bs / Cs split
    for (int idx = tid; idx < 16 * 32; idx += 256) {
        int r = idx >> 5, q = idx & 31;
        float val = dbl_s[r * 40 + 8 + q];
        if (q < 16) g_Bs[(r0 + r) * DS + q]       = val;
        else        g_Cs[(r0 + r) * DS + (q - 16)] = val;
    }
}

// ---------------- scan phase 1: per-chunk (prod dA, local h) ----------------
// grid (16 channel-groups, NCH chunks), 256 threads = 16 ch x 16 states
__global__ void k_scan1(const float* __restrict__ Alog)
{
    __shared__ float dt_s[CT * 16], xc_s[CT * 16], Bs_s[CT * 16];
    int tid = threadIdx.x;
    int chBase = blockIdx.x * 16;
    int c = blockIdx.y;
    int l0 = c * CT;
    for (int idx = tid; idx < CT * 16; idx += 256) {
        int t = idx >> 4, e = idx & 15;
        dt_s[idx] = g_dt[(l0 + t) * DI + chBase + e];
        xc_s[idx] = g_xc[(l0 + t) * DI + chBase + e];
        Bs_s[idx] = g_Bs[(l0 + t) * DS + e];
    }
    __syncthreads();

    int w = tid >> 5, lane = tid & 31;
    int ch = 2 * w + (lane >> 4);
    int s = lane & 15;
    int dG = chBase + ch;
    float negA = -__expf(Alog[dG * DS + s]);

    float h = 0.f, P = 1.f;
    #pragma unroll 4
    for (int t = 0; t < CT; t++) {
        float dtv = dt_s[t * 16 + ch];
        float b   = Bs_s[t * 16 + s];
        float dA  = __expf(dtv * negA);
        P *= dA;
        h = fmaf(dA, h, dtv * xc_s[t * 16 + ch] * b);
    }
    int o = (c * DI + dG) * DS + s;
    g_P[o]  = P;
    g_hN[o] = h;
}

// ---------------- scan phase 2: sequential combine over chunks -------------
__global__ void k_scan2()
{
    int ds = blockIdx.x * 256 + threadIdx.x;   // 0..4095
    float carry = 0.f;
    #pragma unroll 4
    for (int c = 0; c < NCH; c++) {
        g_hin[c * (DI * DS) + ds] = carry;
        carry = fmaf(g_P[c * (DI * DS) + ds], carry, g_hN[c * (DI * DS) + ds]);
    }
}

// ---------------- scan phase 3: replay with carry, produce gated y ---------
__global__ void k_scan3(const float* __restrict__ Alog,
                        const float* __restrict__ Dp)
{
    __shared__ float dt_s[CT * 16], xc_s[CT * 16], zs_s[CT * 16];
    __shared__ float Bs_s[CT * 16], Cs_s[CT * 16];
    int tid = threadIdx.x;
    int chBase = blockIdx.x * 16;
    int c = blockIdx.y;
    int l0 = c * CT;
    for (int idx = tid; idx < CT * 16; idx += 256) {
        int t = idx >> 4, e = idx & 15;
        dt_s[idx] = g_dt[(l0 + t) * DI + chBase + e];
        xc_s[idx] = g_xc[(l0 + t) * DI + chBase + e];
        zs_s[idx] = g_zs[(l0 + t) * DI + chBase + e];
        Bs_s[idx] = g_Bs[(l0 + t) * DS + e];
        Cs_s[idx] = g_Cs[(l0 + t) * DS + e];
    }
    __syncthreads();

    int w = tid >> 5, lane = tid & 31;
    int ch = 2 * w + (lane >> 4);
    int s = lane & 15;
    int dG = chBase + ch;
    float negA  = -__expf(Alog[dG * DS + s]);
    float dskip = Dp[dG];

    float h = g_hin[(c * DI + dG) * DS + s];
    #pragma unroll 4
    for (int t = 0; t < CT; t++) {
        float dtv = dt_s[t * 16 + ch];
        float xcv = xc_s[t * 16 + ch];
        float b   = Bs_s[t * 16 + s];
        float dA  = __expf(dtv * negA);
        h = fmaf(dA, h, dtv * xcv * b);
        float p = h * Cs_s[t * 16 + s];
        p += __shfl_xor_sync(0xffffffffu, p, 8);
        p += __shfl_xor_sync(0xffffffffu, p, 4);
        p += __shfl_xor_sync(0xffffffffu, p, 2);
        p += __shfl_xor_sync(0xffffffffu, p, 1);
        if (s == 0)
            g_y[(l0 + t) * DI + dG] = (p + dskip * xcv) * zs_s[t * 16 + ch];
    }
}

// ---------------- out GEMM + fused RMSNorm ----------------------------------
// M=2304 (16 rows/block), N=128, K=256; 128 threads, one col each
__global__ void k_gemm_out(const float* __restrict__ Wo,
                           const float* __restrict__ rmsw)
{
    __shared__ float y_s[16 * 256];
    __shared__ float red[16 * 4];
    int tid = threadIdx.x;
    int r0 = blockIdx.x * 16;
    for (int idx = tid; idx < 16 * 256; idx += 128)
        y_s[idx] = g_y[r0 * DI + idx];
    __syncthreads();

    float acc[16];
    #pragma unroll
    for (int r = 0; r < 16; r++) acc[r] = 0.f;
    #pragma unroll 2
    for (int k = 0; k < 256; k++) {
        float wv = Wo[k * DM + tid];
        #pragma unroll
        for (int r = 0; r < 16; r++)
            acc[r] = fmaf(y_s[r * 256 + k], wv, acc[r]);
    }

    int lane = tid & 31, w = tid >> 5;
    #pragma unroll
    for (int r = 0; r < 16; r++) {
        float v = acc[r] * acc[r];
        v += __shfl_xor_sync(0xffffffffu, v, 16);
        v += __shfl_xor_sync(0xffffffffu, v, 8);
        v += __shfl_xor_sync(0xffffffffu, v, 4);
        v += __shfl_xor_sync(0xffffffffu, v, 2);
        v += __shfl_xor_sync(0xffffffffu, v, 1);
        if (lane == 0) red[r * 4 + w] = v;
    }
    __syncthreads();

    float rw = rmsw[tid];
    #pragma unroll
    for (int r = 0; r < 16; r++) {
        float ss = red[r * 4 + 0] + red[r * 4 + 1] + red[r * 4 + 2] + red[r * 4 + 3];
        float sc = rsqrtf(ss * (1.0f / 128.0f) + 1e-5f);
        g_seq[(r0 + r) * DM + tid] = acc[r] * sc * rw;
    }
}

// ---------------------------------------------------------------------------
extern "C" void kernel_launch(void* const* d_in, const int* in_sizes, int n_in,
                              void* d_out, int out_size)
{
    const float* x      = (const float*)d_in[0];
    const float* W_in   = (const float*)d_in[1];
    const float* conv_w = (const float*)d_in[2];
    const float* conv_b = (const float*)d_in[3];
    const float* W_xprj = (const float*)d_in[4];
    const float* W_dt   = (const float*)d_in[5];
    const float* b_dt   = (const float*)d_in[6];
    const float* A_log  = (const float*)d_in[7];
    const float* D_skip = (const float*)d_in[8];
    const float* W_out  = (const float*)d_in[9];
    const float* rms_w  = (const float*)d_in[10];
    float* out = (float*)d_out;

    dim3 tb(32, 8);
    k_in_transpose<<<dim3(L_SEQ / 32, DM / 32), tb>>>(x);

    for (int layer = 0; layer < DEPTH; ++layer) {
        const float* Wi  = W_in   + layer * DM * 2 * DI;
        const float* cw  = conv_w + layer * DI * 4;
        const float* cb  = conv_b + layer * DI;
        const float* Wx  = W_xprj + layer * DI * (DR + 2 * DS);
        const float* Wdt = W_dt   + layer * DR * DI;
        const float* bdt = b_dt   + layer * DI;
        const float* Al  = A_log  + layer * DI * DS;
        const float* Dp  = D_skip + layer * DI;
        const float* Wo  = W_out  + layer * DI * DM;
        const float* rw  = rms_w  + layer * DM;

        k_gemm_in  <<<L_SEQ / 16, 256>>>(Wi);
        k_conv_proj<<<L_SEQ / 16, 256>>>(cw, cb, Wx, Wdt, bdt);
        k_scan1    <<<dim3(DI / 16, NCH), 256>>>(Al);
        k_scan2    <<<(DI * DS) / 256, 256>>>();
        k_scan3    <<<dim3(DI / 16, NCH), 256>>>(Al, Dp);
        k_gemm_out <<<L_SEQ / 16, 128>>>(Wo, rw);
    }

    k_out_transpose<<<dim3(DM / 32, L_SEQ / 32), tb>>>(out);
}